// round 12
// baseline (speedup 1.0000x reference)
#include <cuda_runtime.h>
#include <cuda_bf16.h>

// Problem constants
#define B   2
#define NTOK 4100
#define C   768
#define T   4
#define H   12
#define D   64
#define K   2
#define M   4096          // NTOK - T
#define J   48            // H*T query rows per batch
#define SCALE 0.125f      // d^-0.5

#define CSP  4            // c-splits for k_attn
#define CPER (C / CSP)    // 192 channels per split
#define MT   8            // m-tiles for top2 stage-1
#define MTS  (M / MT)     // 512 elements per tile

// ---------------- scratch (device globals; no allocations allowed) ----------
__device__ float g_q[B * T * C];                 // q[b,t,o]
__device__ float g_qk[B * J * C];                // qk[b, h*4+t, c]
__device__ float g_attn2[CSP][B * J * M];        // c-split partial attn
__device__ volatile float g_cv[B * J][MT][2];    // stage-1 top2 candidates (val)
__device__ volatile int   g_ci[B * J][MT][2];    // stage-1 top2 candidates (idx)
__device__ int   g_ticket[B * J];                // last-CTA tickets (self-reset)
__device__ int   g_topi[B * J * K];
__device__ float g_topw[B * J * K];

// ---------------- helpers ---------------------------------------------------
__device__ __forceinline__ void ffma2(unsigned long long &d,
                                      unsigned long long a,
                                      unsigned long long b) {
    asm("fma.rn.f32x2 %0, %1, %2, %0;" : "+l"(d) : "l"(a), "l"(b));
}

union U64F2 { unsigned long long u; float2 f; };

__device__ __forceinline__ float warp_sum(float s) {
    #pragma unroll
    for (int off = 16; off; off >>= 1) s += __shfl_xor_sync(0xffffffffu, s, off);
    return s;
}

__device__ __forceinline__ void cp8(unsigned dst, const float* src) {
    asm volatile("cp.async.ca.shared.global [%0], [%1], 8;\n"
                 :: "r"(dst), "l"(__cvta_generic_to_global(src)) : "memory");
}

// ---------------- K1: q[b,t,o] = <x[b,t,:], qs_w[t,o,:]> --------------------
// grid 384 = (t, o-group of 8). One output per warp, both batches.
__global__ __launch_bounds__(256) void k_q(const float* __restrict__ x,
                                           const float* __restrict__ qs_w) {
    int og = blockIdx.x % 96;
    int t  = blockIdx.x / 96;
    __shared__ float xs[2 * C];
    for (int i = threadIdx.x; i < 2 * C; i += 256) {
        int b = i / C, c = i % C;
        xs[i] = x[((long)b * NTOK + t) * C + c];
    }
    __syncthreads();
    int warp = threadIdx.x >> 5, lane = threadIdx.x & 31;
    int o = og * 8 + warp;
    const float* wrow = qs_w + ((long)t * C + o) * C;
    float s0 = 0.f, s1 = 0.f;
    #pragma unroll 8
    for (int c = lane; c < C; c += 32) {
        float w = wrow[c];
        s0 += xs[c] * w;
        s1 += xs[C + c] * w;
    }
    s0 = warp_sum(s0);
    s1 = warp_sum(s1);
    if (lane == 0) {
        g_q[(0 * T + t) * C + o] = s0;
        g_q[(1 * T + t) * C + o] = s1;
    }
}

// ---------------- K2: qk[b,j,c] = sum_dd q[b,t,h*64+dd] * kv_w[h*64+dd, c] --
// grid 288 = (j, c-chunk of 128), 128 threads. Both batches per block.
__global__ __launch_bounds__(128) void k_qk(const float* __restrict__ kv_w) {
    int ch = blockIdx.x % 6;
    int j  = blockIdx.x / 6;
    int t = j & 3, h = j >> 2;
    __shared__ float qs[2 * D];
    {
        int b = threadIdx.x >> 6, dd = threadIdx.x & 63;
        qs[threadIdx.x] = g_q[(b * T + t) * C + h * D + dd];
    }
    __syncthreads();
    int c = ch * 128 + threadIdx.x;
    float a0 = 0.f, a1 = 0.f;
    #pragma unroll 8
    for (int dd = 0; dd < D; dd++) {
        float w = kv_w[(long)(h * D + dd) * C + c];
        a0 += qs[dd] * w;
        a1 += qs[D + dd] * w;
    }
    g_qk[((long)(0 * J + j)) * C + c] = a0;
    g_qk[((long)(1 * J + j)) * C + c] = a1;
}

// ---------------- K3: partial attn over a c-quarter -------------------------
// grid (64 m-tiles, B, 4 c-quarters) = 512 CTAs, occ 4.
#define CHUNK 32
#define NCH   (CPER / CHUNK)           // 6
#define QK_FL (48 * CHUNK)             // 1536
#define FSTR  34
#define STAGE_FL (QK_FL + 64 * FSTR)   // 3712 floats = 14848 B/stage
__global__ __launch_bounds__(256, 4) void k_attn(const float* __restrict__ x) {
    extern __shared__ __align__(16) float sm[];   // 2 * STAGE_FL floats
    const int b  = blockIdx.y;
    const int m0 = blockIdx.x * 64;
    const int cs = blockIdx.z;
    const int tid  = threadIdx.x;
    const int warp = tid >> 5;
    const int lane = tid & 31;
    const int cr = tid >> 4;      // copy row base 0..15
    const int cp0 = tid & 15;     // copy pair    0..15

    const float* qsrc0 = g_qk + (long)b * J * C + cs * CPER
                       + (long)cr * C + cp0 * 2;               // +u*16*C
    const float* fsrc0 = x + ((long)b * NTOK + T + m0) * C + cs * CPER
                       + (long)cr * C + cp0 * 2;               // +u*16*C
    unsigned qdst0 = (unsigned)__cvta_generic_to_shared(
                         &sm[cr * CHUNK + cp0 * 2]);           // +u*2048B
    unsigned fdst0 = (unsigned)__cvta_generic_to_shared(
                         &sm[QK_FL + cr * FSTR + cp0 * 2]);    // +u*2176B

    unsigned long long acc[6][2];
    #pragma unroll
    for (int i = 0; i < 6; i++) { acc[i][0] = 0ull; acc[i][1] = 0ull; }

    #pragma unroll
    for (int u = 0; u < 3; u++) cp8(qdst0 + u * 2048, qsrc0 + u * 16 * C);
    #pragma unroll
    for (int u = 0; u < 4; u++) cp8(fdst0 + u * 2176, fsrc0 + u * 16 * C);
    asm volatile("cp.async.commit_group;\n" ::: "memory");

    for (int ic = 0; ic < NCH; ic++) {
        if (ic < NCH - 1) {
            unsigned so = ((ic + 1) & 1) * (unsigned)(STAGE_FL * 4);
            int cc = (ic + 1) * CHUNK;
            #pragma unroll
            for (int u = 0; u < 3; u++)
                cp8(qdst0 + so + u * 2048, qsrc0 + cc + u * 16 * C);
            #pragma unroll
            for (int u = 0; u < 4; u++)
                cp8(fdst0 + so + u * 2176, fsrc0 + cc + u * 16 * C);
            asm volatile("cp.async.commit_group;\n" ::: "memory");
            asm volatile("cp.async.wait_group 1;\n" ::: "memory");
        } else {
            asm volatile("cp.async.wait_group 0;\n" ::: "memory");
        }
        __syncthreads();
        const float* s_qk = sm + (ic & 1) * STAGE_FL;
        const float* s_ft = s_qk + QK_FL;
        #pragma unroll
        for (int cp = 0; cp < 16; cp++) {
            unsigned long long f0 =
                *(const unsigned long long*)&s_ft[lane * FSTR + cp * 2];
            unsigned long long f1 =
                *(const unsigned long long*)&s_ft[(lane + 32) * FSTR + cp * 2];
            #pragma unroll
            for (int i = 0; i < 6; i++) {
                unsigned long long qv =
                    *(const unsigned long long*)&s_qk[(warp * 6 + i) * CHUNK + cp * 2];
                ffma2(acc[i][0], qv, f0);
                ffma2(acc[i][1], qv, f1);
            }
        }
        __syncthreads();
    }
    #pragma unroll
    for (int i = 0; i < 6; i++) {
        int j = warp * 6 + i;
        float* row = g_attn2[cs] + ((long)(b * J + j)) * M + m0;
        U64F2 u0; u0.u = acc[i][0];
        U64F2 u1; u1.u = acc[i][1];
        row[lane]      = (u0.f.x + u0.f.y) * SCALE;
        row[lane + 32] = (u1.f.x + u1.f.y) * SCALE;
    }
}

// ---------------- K4: fused two-stage top-2 + softmax -----------------------
__device__ __forceinline__ bool better(float v, int i, float bv, int bi) {
    return (v > bv) || (v == bv && (unsigned)i < (unsigned)bi);
}
// merge sorted pair (v0>=v1) with sorted pair (c0>=c1); indices all distinct
__device__ __forceinline__ void merge2(float &v0, int &i0, float &v1, int &i1,
                                       float c0, int jc, float c1, int jd) {
    float n0, n1; int m0i, m1i;
    if (better(v0, i0, c0, jc)) {
        n0 = v0; m0i = i0;
        if (better(v1, i1, c0, jc)) { n1 = v1; m1i = i1; }
        else                        { n1 = c0; m1i = jc; }
    } else {
        n0 = c0; m0i = jc;
        if (better(v0, i0, c1, jd)) { n1 = v0; m1i = i0; }
        else                        { n1 = c1; m1i = jd; }
    }
    v0 = n0; i0 = m0i; v1 = n1; i1 = m1i;
}

__global__ __launch_bounds__(128) void k_top2() {
    const int row   = blockIdx.y;          // 0..95
    const int mtile = blockIdx.x;          // 0..7
    const long base = (long)row * M + mtile * MTS;
    int tid = threadIdx.x, warp = tid >> 5, lane = tid & 31;
    int mm = tid * 4;                      // 0..508 within tile
    float4 a0 = *(const float4*)(g_attn2[0] + base + mm);
    float4 a1 = *(const float4*)(g_attn2[1] + base + mm);
    float4 a2 = *(const float4*)(g_attn2[2] + base + mm);
    float4 a3 = *(const float4*)(g_attn2[3] + base + mm);
    int gm = mtile * MTS + mm;
    float s0 = (a0.x + a1.x) + (a2.x + a3.x);
    float s1 = (a0.y + a1.y) + (a2.y + a3.y);
    float s2 = (a0.z + a1.z) + (a2.z + a3.z);
    float s3 = (a0.w + a1.w) + (a2.w + a3.w);
    // sort (s0,s1) and (s2,s3) into pairs, then merge (FIX: both pairs sorted)
    float v0, v1; int i0, i1;
    if (better(s1, gm + 1, s0, gm)) { v0 = s1; i0 = gm + 1; v1 = s0; i1 = gm; }
    else                            { v0 = s0; i0 = gm;     v1 = s1; i1 = gm + 1; }
    float c0, c1; int jc, jd;
    if (better(s3, gm + 3, s2, gm + 2)) { c0 = s3; jc = gm + 3; c1 = s2; jd = gm + 2; }
    else                                { c0 = s2; jc = gm + 2; c1 = s3; jd = gm + 3; }
    merge2(v0, i0, v1, i1, c0, jc, c1, jd);
    // warp shuffle merge (both sides always sorted pairs)
    #pragma unroll
    for (int s = 16; s >= 1; s >>= 1) {
        float p0 = __shfl_down_sync(0xffffffffu, v0, s);
        float p1 = __shfl_down_sync(0xffffffffu, v1, s);
        int   q0 = __shfl_down_sync(0xffffffffu, i0, s);
        int   q1 = __shfl_down_sync(0xffffffffu, i1, s);
        merge2(v0, i0, v1, i1, p0, q0, p1, q1);
    }
    __shared__ float wv0[4], wv1[4];
    __shared__ int   wi0[4], wi1[4];
    if (lane == 0) { wv0[warp] = v0; wi0[warp] = i0; wv1[warp] = v1; wi1[warp] = i1; }
    __syncthreads();
    if (warp == 0) {
        if (lane < 4) { v0 = wv0[lane]; i0 = wi0[lane]; v1 = wv1[lane]; i1 = wi1[lane]; }
        #pragma unroll
        for (int s = 2; s >= 1; s >>= 1) {
            float p0 = __shfl_down_sync(0xffffffffu, v0, s);
            float p1 = __shfl_down_sync(0xffffffffu, v1, s);
            int   q0 = __shfl_down_sync(0xffffffffu, i0, s);
            int   q1 = __shfl_down_sync(0xffffffffu, i1, s);
            merge2(v0, i0, v1, i1, p0, q0, p1, q1);
        }
        if (lane == 0) {
            g_cv[row][mtile][0] = v0;  g_cv[row][mtile][1] = v1;
            g_ci[row][mtile][0] = i0;  g_ci[row][mtile][1] = i1;
            __threadfence();
            int old = atomicAdd(&g_ticket[row], 1);
            if (old == MT - 1) {
                // last CTA of this row: merge all 8 sorted candidate pairs
                __threadfence();
                float b0 = g_cv[row][0][0], b1 = g_cv[row][0][1];
                int   j0 = g_ci[row][0][0], j1 = g_ci[row][0][1];
                #pragma unroll
                for (int e = 1; e < MT; e++)
                    merge2(b0, j0, b1, j1,
                           g_cv[row][e][0], g_ci[row][e][0],
                           g_cv[row][e][1], g_ci[row][e][1]);
                float e1 = __expf(b1 - b0);
                float inv = 1.f / (1.f + e1);
                g_topi[row * K + 0] = j0;
                g_topi[row * K + 1] = j1;
                g_topw[row * K + 0] = inv;
                g_topw[row * K + 1] = e1 * inv;
                g_ticket[row] = 0;    // self-reset for next graph replay
            }
        }
    }
}

// ---------------- K5: selections + expert scatter + fused token output ------
// grid 96 = (b,j=(h,t)). Produces:
//   out[b, 4+m_k, o] += w_k * <f_k[hD:+64], ew[t,o,hD:+64]>     (k=0,1)
//   out[b,   t,  o]  += <slice_h, ew[t,o,hD:+64]>               (token partial)
// where slice_h[dd] = w0*<f0,kv_w[C+hD+dd,:]> + w1*<f1,...>.
__global__ __launch_bounds__(256) void k_select(const float* __restrict__ x,
                                                const float* __restrict__ kv_w,
                                                const float* __restrict__ experts_w,
                                                float* __restrict__ out) {
    int b = blockIdx.x / J;
    int j = blockIdx.x % J;
    int t = j & 3, h = j >> 2;
    int   m0 = g_topi[(b * J + j) * K + 0];
    int   m1 = g_topi[(b * J + j) * K + 1];
    float w0 = g_topw[(b * J + j) * K + 0];
    float w1 = g_topw[(b * J + j) * K + 1];
    int warp = threadIdx.x >> 5, lane = threadIdx.x & 31;
    __shared__ __align__(16) float f0s[C], f1s[C], slice[D];
    for (int i = threadIdx.x; i < C; i += 256) {
        f0s[i] = x[((long)b * NTOK + T + m0) * C + i];
        f1s[i] = x[((long)b * NTOK + T + m1) * C + i];
    }
    __syncthreads();

    // (a) v rows dd = warp*8 + i, all 8 rows in one c-pass (MLP 8)
    {
        const float* kw = kv_w + (long)(C + h * D + warp * 8) * C;
        float a0[8], a1[8];
        #pragma unroll
        for (int i = 0; i < 8; i++) { a0[i] = 0.f; a1[i] = 0.f; }
        #pragma unroll 2
        for (int c = lane; c < C; c += 32) {
            float f0 = f0s[c], f1 = f1s[c];
            #pragma unroll
            for (int i = 0; i < 8; i++) {
                float w = kw[(long)i * C + c];
                a0[i] += f0 * w;
                a1[i] += f1 * w;
            }
        }
        #pragma unroll
        for (int i = 0; i < 8; i++) {
            float s0 = warp_sum(a0[i]);
            float s1 = warp_sum(a1[i]);
            if (lane == 0) slice[warp * 8 + i] = w0 * s0 + w1 * s1;
        }
    }
    __syncthreads();

    // (b) expert projection: each ew row read once; 3 dots per o
    const float4* f04 = (const float4*)(f0s + h * D);
    const float4* f14 = (const float4*)(f1s + h * D);
    const float4* sl4 = (const float4*)slice;
    float* outb = out + (long)b * NTOK * C;
    for (int o = threadIdx.x; o < C; o += 256) {
        const float4* ew4 =
            (const float4*)(experts_w + ((long)t * C + o) * C + h * D);
        float s0 = 0.f, s1 = 0.f, st = 0.f;
        #pragma unroll
        for (int q = 0; q < 16; q++) {
            float4 e = ew4[q];
            float4 u = f04[q], v = f14[q], w = sl4[q];
            s0 += u.x * e.x + u.y * e.y + u.z * e.z + u.w * e.w;
            s1 += v.x * e.x + v.y * e.y + v.z * e.z + v.w * e.w;
            st += w.x * e.x + w.y * e.y + w.z * e.z + w.w * e.w;
        }
        atomicAdd(&outb[(long)(T + m0) * C + o], w0 * s0);
        atomicAdd(&outb[(long)(T + m1) * C + o], w1 * s1);
        atomicAdd(&outb[(long)t * C + o], st);
    }
}

// ---------------- launch ----------------------------------------------------
extern "C" void kernel_launch(void* const* d_in, const int* in_sizes, int n_in,
                              void* d_out, int out_size) {
    const float* x         = (const float*)d_in[0];
    const float* qs_w      = (const float*)d_in[1];
    const float* kv_w      = (const float*)d_in[2];
    const float* experts_w = (const float*)d_in[3];
    float* out = (float*)d_out;

    cudaMemsetAsync(out, 0, (size_t)out_size * sizeof(float));
    k_q<<<384, 256>>>(x, qs_w);
    k_qk<<<288, 128>>>(kv_w);
    k_attn<<<dim3(64, B, CSP), 256, 2 * STAGE_FL * 4>>>(x);
    k_top2<<<dim3(MT, B * J), 128>>>();
    k_select<<<96, 256>>>(x, kv_w, experts_w, out);
}

// round 13
// speedup vs baseline: 1.0436x; 1.0436x over previous
#include <cuda_runtime.h>
#include <cuda_bf16.h>

// Problem constants
#define B   2
#define NTOK 4100
#define C   768
#define T   4
#define H   12
#define D   64
#define K   2
#define M   4096          // NTOK - T
#define J   48            // H*T query rows per batch
#define SCALE 0.125f      // d^-0.5

#define CSP  4            // c-splits for k_attn
#define CPER (C / CSP)    // 192 channels per split
#define MT   8            // m-tiles for top2 stage-1
#define MTS  (M / MT)     // 512 elements per tile
#define ZPB  2050         // float4s of output zeroed per top2 CTA (exact: 1574400/768)

// ---------------- scratch (device globals; no allocations allowed) ----------
__device__ float g_q[B * T * C];                 // q[b,t,o]
__device__ float g_qk[B * J * C];                // qk[b, h*4+t, c]
__device__ float g_attn2[CSP][B * J * M];        // c-split partial attn
__device__ volatile float g_cv[B * J][MT][2];    // stage-1 top2 candidates (val)
__device__ volatile int   g_ci[B * J][MT][2];    // stage-1 top2 candidates (idx)
__device__ int   g_ticket[B * J];                // last-CTA tickets (self-reset)
__device__ int   g_topi[B * J * K];
__device__ float g_topw[B * J * K];

// ---------------- helpers ---------------------------------------------------
__device__ __forceinline__ void ffma2(unsigned long long &d,
                                      unsigned long long a,
                                      unsigned long long b) {
    asm("fma.rn.f32x2 %0, %1, %2, %0;" : "+l"(d) : "l"(a), "l"(b));
}

union U64F2 { unsigned long long u; float2 f; };

__device__ __forceinline__ float warp_sum(float s) {
    #pragma unroll
    for (int off = 16; off; off >>= 1) s += __shfl_xor_sync(0xffffffffu, s, off);
    return s;
}

__device__ __forceinline__ void cp8(unsigned dst, const float* src) {
    asm volatile("cp.async.ca.shared.global [%0], [%1], 8;\n"
                 :: "r"(dst), "l"(__cvta_generic_to_global(src)) : "memory");
}

// ---------------- K1: q[b,t,o] = <x[b,t,:], qs_w[t,o,:]> --------------------
// grid 384 = (t, o-group of 8). One output per warp, both batches.
__global__ __launch_bounds__(256) void k_q(const float* __restrict__ x,
                                           const float* __restrict__ qs_w) {
    int og = blockIdx.x % 96;
    int t  = blockIdx.x / 96;
    __shared__ float xs[2 * C];
    for (int i = threadIdx.x; i < 2 * C; i += 256) {
        int b = i / C, c = i % C;
        xs[i] = x[((long)b * NTOK + t) * C + c];
    }
    __syncthreads();
    int warp = threadIdx.x >> 5, lane = threadIdx.x & 31;
    int o = og * 8 + warp;
    const float* wrow = qs_w + ((long)t * C + o) * C;
    float s0 = 0.f, s1 = 0.f;
    #pragma unroll 8
    for (int c = lane; c < C; c += 32) {
        float w = wrow[c];
        s0 += xs[c] * w;
        s1 += xs[C + c] * w;
    }
    s0 = warp_sum(s0);
    s1 = warp_sum(s1);
    if (lane == 0) {
        g_q[(0 * T + t) * C + o] = s0;
        g_q[(1 * T + t) * C + o] = s1;
    }
}

// ---------------- K2: qk[b,j,c] = sum_dd q[b,t,h*64+dd] * kv_w[h*64+dd, c] --
// grid 288 = (j, c-chunk of 128), 128 threads. Both batches per block.
__global__ __launch_bounds__(128) void k_qk(const float* __restrict__ kv_w) {
    int ch = blockIdx.x % 6;
    int j  = blockIdx.x / 6;
    int t = j & 3, h = j >> 2;
    __shared__ float qs[2 * D];
    {
        int b = threadIdx.x >> 6, dd = threadIdx.x & 63;
        qs[threadIdx.x] = g_q[(b * T + t) * C + h * D + dd];
    }
    __syncthreads();
    int c = ch * 128 + threadIdx.x;
    float a0 = 0.f, a1 = 0.f;
    #pragma unroll 8
    for (int dd = 0; dd < D; dd++) {
        float w = kv_w[(long)(h * D + dd) * C + c];
        a0 += qs[dd] * w;
        a1 += qs[D + dd] * w;
    }
    g_qk[((long)(0 * J + j)) * C + c] = a0;
    g_qk[((long)(1 * J + j)) * C + c] = a1;
}

// ---------------- K3: partial attn over a c-quarter -------------------------
// grid (64 m-tiles, B, 4 c-quarters) = 512 CTAs, occ 4.
#define CHUNK 32
#define NCH   (CPER / CHUNK)           // 6
#define QK_FL (48 * CHUNK)             // 1536
#define FSTR  34
#define STAGE_FL (QK_FL + 64 * FSTR)   // 3712 floats = 14848 B/stage
__global__ __launch_bounds__(256, 4) void k_attn(const float* __restrict__ x) {
    extern __shared__ __align__(16) float sm[];   // 2 * STAGE_FL floats
    const int b  = blockIdx.y;
    const int m0 = blockIdx.x * 64;
    const int cs = blockIdx.z;
    const int tid  = threadIdx.x;
    const int warp = tid >> 5;
    const int lane = tid & 31;
    const int cr = tid >> 4;      // copy row base 0..15
    const int cp0 = tid & 15;     // copy pair    0..15

    const float* qsrc0 = g_qk + (long)b * J * C + cs * CPER
                       + (long)cr * C + cp0 * 2;               // +u*16*C
    const float* fsrc0 = x + ((long)b * NTOK + T + m0) * C + cs * CPER
                       + (long)cr * C + cp0 * 2;               // +u*16*C
    unsigned qdst0 = (unsigned)__cvta_generic_to_shared(
                         &sm[cr * CHUNK + cp0 * 2]);           // +u*2048B
    unsigned fdst0 = (unsigned)__cvta_generic_to_shared(
                         &sm[QK_FL + cr * FSTR + cp0 * 2]);    // +u*2176B

    unsigned long long acc[6][2];
    #pragma unroll
    for (int i = 0; i < 6; i++) { acc[i][0] = 0ull; acc[i][1] = 0ull; }

    #pragma unroll
    for (int u = 0; u < 3; u++) cp8(qdst0 + u * 2048, qsrc0 + u * 16 * C);
    #pragma unroll
    for (int u = 0; u < 4; u++) cp8(fdst0 + u * 2176, fsrc0 + u * 16 * C);
    asm volatile("cp.async.commit_group;\n" ::: "memory");

    for (int ic = 0; ic < NCH; ic++) {
        if (ic < NCH - 1) {
            unsigned so = ((ic + 1) & 1) * (unsigned)(STAGE_FL * 4);
            int cc = (ic + 1) * CHUNK;
            #pragma unroll
            for (int u = 0; u < 3; u++)
                cp8(qdst0 + so + u * 2048, qsrc0 + cc + u * 16 * C);
            #pragma unroll
            for (int u = 0; u < 4; u++)
                cp8(fdst0 + so + u * 2176, fsrc0 + cc + u * 16 * C);
            asm volatile("cp.async.commit_group;\n" ::: "memory");
            asm volatile("cp.async.wait_group 1;\n" ::: "memory");
        } else {
            asm volatile("cp.async.wait_group 0;\n" ::: "memory");
        }
        __syncthreads();
        const float* s_qk = sm + (ic & 1) * STAGE_FL;
        const float* s_ft = s_qk + QK_FL;
        #pragma unroll
        for (int cp = 0; cp < 16; cp++) {
            unsigned long long f0 =
                *(const unsigned long long*)&s_ft[lane * FSTR + cp * 2];
            unsigned long long f1 =
                *(const unsigned long long*)&s_ft[(lane + 32) * FSTR + cp * 2];
            #pragma unroll
            for (int i = 0; i < 6; i++) {
                unsigned long long qv =
                    *(const unsigned long long*)&s_qk[(warp * 6 + i) * CHUNK + cp * 2];
                ffma2(acc[i][0], qv, f0);
                ffma2(acc[i][1], qv, f1);
            }
        }
        __syncthreads();
    }
    #pragma unroll
    for (int i = 0; i < 6; i++) {
        int j = warp * 6 + i;
        float* row = g_attn2[cs] + ((long)(b * J + j)) * M + m0;
        U64F2 u0; u0.u = acc[i][0];
        U64F2 u1; u1.u = acc[i][1];
        row[lane]      = (u0.f.x + u0.f.y) * SCALE;
        row[lane + 32] = (u1.f.x + u1.f.y) * SCALE;
    }
}

// ---------------- K4: fused top-2 + softmax + output zeroing ----------------
__device__ __forceinline__ bool better(float v, int i, float bv, int bi) {
    return (v > bv) || (v == bv && (unsigned)i < (unsigned)bi);
}
// merge sorted pair (v0>=v1) with sorted pair (c0>=c1); indices all distinct
__device__ __forceinline__ void merge2(float &v0, int &i0, float &v1, int &i1,
                                       float c0, int jc, float c1, int jd) {
    float n0, n1; int m0i, m1i;
    if (better(v0, i0, c0, jc)) {
        n0 = v0; m0i = i0;
        if (better(v1, i1, c0, jc)) { n1 = v1; m1i = i1; }
        else                        { n1 = c0; m1i = jc; }
    } else {
        n0 = c0; m0i = jc;
        if (better(v0, i0, c1, jd)) { n1 = v0; m1i = i0; }
        else                        { n1 = c1; m1i = jd; }
    }
    v0 = n0; i0 = m0i; v1 = n1; i1 = m1i;
}

__global__ __launch_bounds__(256) void k_top2(float4* __restrict__ out4) {
    const int row   = blockIdx.y;          // 0..95
    const int mtile = blockIdx.x;          // 0..7
    const long base = (long)row * M + mtile * MTS;
    int tid = threadIdx.x, warp = tid >> 5, lane = tid & 31;
    int mm = tid * 2;                      // 0..510 within tile
    float2 a0 = *(const float2*)(g_attn2[0] + base + mm);
    float2 a1 = *(const float2*)(g_attn2[1] + base + mm);
    float2 a2 = *(const float2*)(g_attn2[2] + base + mm);
    float2 a3 = *(const float2*)(g_attn2[3] + base + mm);
    int gm = mtile * MTS + mm;
    float s0 = (a0.x + a1.x) + (a2.x + a3.x);
    float s1 = (a0.y + a1.y) + (a2.y + a3.y);
    float v0, v1; int i0, i1;
    if (better(s1, gm + 1, s0, gm)) { v0 = s1; i0 = gm + 1; v1 = s0; i1 = gm; }
    else                            { v0 = s0; i0 = gm;     v1 = s1; i1 = gm + 1; }

    // zero this CTA's slice of the output (independent of the reduction)
    {
        long zbase = (long)(row * MT + mtile) * ZPB;
        float4 z = make_float4(0.f, 0.f, 0.f, 0.f);
        #pragma unroll
        for (int u = 0; u < 8; u++) out4[zbase + u * 256 + tid] = z;
        if (tid < ZPB - 8 * 256) out4[zbase + 8 * 256 + tid] = z;
    }

    // warp shuffle merge (both sides always sorted pairs)
    #pragma unroll
    for (int s = 16; s >= 1; s >>= 1) {
        float p0 = __shfl_down_sync(0xffffffffu, v0, s);
        float p1 = __shfl_down_sync(0xffffffffu, v1, s);
        int   q0 = __shfl_down_sync(0xffffffffu, i0, s);
        int   q1 = __shfl_down_sync(0xffffffffu, i1, s);
        merge2(v0, i0, v1, i1, p0, q0, p1, q1);
    }
    __shared__ float wv0[8], wv1[8];
    __shared__ int   wi0[8], wi1[8];
    if (lane == 0) { wv0[warp] = v0; wi0[warp] = i0; wv1[warp] = v1; wi1[warp] = i1; }
    __syncthreads();
    if (warp == 0) {
        if (lane < 8) { v0 = wv0[lane]; i0 = wi0[lane]; v1 = wv1[lane]; i1 = wi1[lane]; }
        #pragma unroll
        for (int s = 4; s >= 1; s >>= 1) {
            float p0 = __shfl_down_sync(0xffffffffu, v0, s);
            float p1 = __shfl_down_sync(0xffffffffu, v1, s);
            int   q0 = __shfl_down_sync(0xffffffffu, i0, s);
            int   q1 = __shfl_down_sync(0xffffffffu, i1, s);
            merge2(v0, i0, v1, i1, p0, q0, p1, q1);
        }
        if (lane == 0) {
            g_cv[row][mtile][0] = v0;  g_cv[row][mtile][1] = v1;
            g_ci[row][mtile][0] = i0;  g_ci[row][mtile][1] = i1;
            __threadfence();
            int old = atomicAdd(&g_ticket[row], 1);
            if (old == MT - 1) {
                __threadfence();
                float b0 = g_cv[row][0][0], b1 = g_cv[row][0][1];
                int   j0 = g_ci[row][0][0], j1 = g_ci[row][0][1];
                #pragma unroll
                for (int e = 1; e < MT; e++)
                    merge2(b0, j0, b1, j1,
                           g_cv[row][e][0], g_ci[row][e][0],
                           g_cv[row][e][1], g_ci[row][e][1]);
                float e1 = __expf(b1 - b0);
                float inv = 1.f / (1.f + e1);
                g_topi[row * K + 0] = j0;
                g_topi[row * K + 1] = j1;
                g_topw[row * K + 0] = inv;
                g_topw[row * K + 1] = e1 * inv;
                g_ticket[row] = 0;    // self-reset for next graph replay
            }
        }
    }
}

// ---------------- K5: selections + expert scatter + fused token output ------
// grid 96 = (b,j=(h,t)). Produces:
//   out[b, 4+m_k, o] += w_k * <f_k[hD:+64], ew[t,o,hD:+64]>     (k=0,1)
//   out[b,   t,  o]  += <slice_h, ew[t,o,hD:+64]>               (token partial)
// where slice_h[dd] = w0*<f0,kv_w[C+hD+dd,:]> + w1*<f1,...>.
__global__ __launch_bounds__(256) void k_select(const float* __restrict__ x,
                                                const float* __restrict__ kv_w,
                                                const float* __restrict__ experts_w,
                                                float* __restrict__ out) {
    int b = blockIdx.x / J;
    int j = blockIdx.x % J;
    int t = j & 3, h = j >> 2;
    int   m0 = g_topi[(b * J + j) * K + 0];
    int   m1 = g_topi[(b * J + j) * K + 1];
    float w0 = g_topw[(b * J + j) * K + 0];
    float w1 = g_topw[(b * J + j) * K + 1];
    int warp = threadIdx.x >> 5, lane = threadIdx.x & 31;
    __shared__ __align__(16) float f0s[C], f1s[C], slice[D];
    for (int i = threadIdx.x; i < C; i += 256) {
        f0s[i] = x[((long)b * NTOK + T + m0) * C + i];
        f1s[i] = x[((long)b * NTOK + T + m1) * C + i];
    }
    __syncthreads();

    // (a) v rows dd = warp*8 + i, all 8 rows in one c-pass (MLP 8)
    {
        const float* kw = kv_w + (long)(C + h * D + warp * 8) * C;
        float a0[8], a1[8];
        #pragma unroll
        for (int i = 0; i < 8; i++) { a0[i] = 0.f; a1[i] = 0.f; }
        #pragma unroll 2
        for (int c = lane; c < C; c += 32) {
            float f0 = f0s[c], f1 = f1s[c];
            #pragma unroll
            for (int i = 0; i < 8; i++) {
                float w = kw[(long)i * C + c];
                a0[i] += f0 * w;
                a1[i] += f1 * w;
            }
        }
        #pragma unroll
        for (int i = 0; i < 8; i++) {
            float s0 = warp_sum(a0[i]);
            float s1 = warp_sum(a1[i]);
            if (lane == 0) slice[warp * 8 + i] = w0 * s0 + w1 * s1;
        }
    }
    __syncthreads();

    // (b) expert projection: each ew row read once; 3 dots per o
    const float4* f04 = (const float4*)(f0s + h * D);
    const float4* f14 = (const float4*)(f1s + h * D);
    const float4* sl4 = (const float4*)slice;
    float* outb = out + (long)b * NTOK * C;
    for (int o = threadIdx.x; o < C; o += 256) {
        const float4* ew4 =
            (const float4*)(experts_w + ((long)t * C + o) * C + h * D);
        float s0 = 0.f, s1 = 0.f, st = 0.f;
        #pragma unroll
        for (int q = 0; q < 16; q++) {
            float4 e = ew4[q];
            float4 u = f04[q], v = f14[q], w = sl4[q];
            s0 += u.x * e.x + u.y * e.y + u.z * e.z + u.w * e.w;
            s1 += v.x * e.x + v.y * e.y + v.z * e.z + v.w * e.w;
            st += w.x * e.x + w.y * e.y + w.z * e.z + w.w * e.w;
        }
        atomicAdd(&outb[(long)(T + m0) * C + o], w0 * s0);
        atomicAdd(&outb[(long)(T + m1) * C + o], w1 * s1);
        atomicAdd(&outb[(long)t * C + o], st);
    }
}

// ---------------- launch ----------------------------------------------------
extern "C" void kernel_launch(void* const* d_in, const int* in_sizes, int n_in,
                              void* d_out, int out_size) {
    const float* x         = (const float*)d_in[0];
    const float* qs_w      = (const float*)d_in[1];
    const float* kv_w      = (const float*)d_in[2];
    const float* experts_w = (const float*)d_in[3];
    float* out = (float*)d_out;

    k_q<<<384, 256>>>(x, qs_w);
    k_qk<<<288, 128>>>(kv_w);
    k_attn<<<dim3(64, B, CSP), 256, 2 * STAGE_FL * 4>>>(x);
    k_top2<<<dim3(MT, B * J), 256>>>((float4*)out);
    k_select<<<96, 256>>>(x, kv_w, experts_w, out);
}

// round 17
// speedup vs baseline: 1.2046x; 1.1543x over previous
#include <cuda_runtime.h>
#include <cuda_bf16.h>

// Problem constants
#define B   2
#define NTOK 4100
#define C   768
#define T   4
#define H   12
#define D   64
#define K   2
#define M   4096          // NTOK - T
#define J   48            // H*T query rows per batch
#define SCALE 0.125f      // d^-0.5

#define CSP  4            // c-splits for k_attn
#define CPER (C / CSP)    // 192 channels per split
#define MT   8            // m-tiles for top2 stage-1
#define MTS  (M / MT)     // 512 elements per tile
#define Z4CTA 3075        // float4s zeroed per k_attn CTA (1574400/512 exact)

// ---------------- scratch (device globals; no allocations allowed) ----------
__device__ float g_q[B * T * C];                 // q[b,t,o]
__device__ float g_qk[B * J * C];                // qk[b, h*4+t, c]
__device__ float g_attn2[CSP][B * J * M];        // c-split partial attn
__device__ volatile float g_cv[B * J][MT][2];    // stage-1 top2 candidates (val)
__device__ volatile int   g_ci[B * J][MT][2];    // stage-1 top2 candidates (idx)
__device__ int   g_ticket[B * J];                // last-CTA tickets (self-reset)
__device__ int   g_topi[B * J * K];
__device__ float g_topw[B * J * K];
__device__ float g_slice[B * H * T * D];         // weighted v-slices

// ---------------- helpers ---------------------------------------------------
__device__ __forceinline__ void ffma2(unsigned long long &d,
                                      unsigned long long a,
                                      unsigned long long b) {
    asm("fma.rn.f32x2 %0, %1, %2, %0;" : "+l"(d) : "l"(a), "l"(b));
}

union U64F2 { unsigned long long u; float2 f; };

__device__ __forceinline__ float warp_sum(float s) {
    #pragma unroll
    for (int off = 16; off; off >>= 1) s += __shfl_xor_sync(0xffffffffu, s, off);
    return s;
}

__device__ __forceinline__ void cp8(unsigned dst, const float* src) {
    asm volatile("cp.async.ca.shared.global [%0], [%1], 8;\n"
                 :: "r"(dst), "l"(__cvta_generic_to_global(src)) : "memory");
}

// ---------------- K1: q[b,t,o] = <x[b,t,:], qs_w[t,o,:]> --------------------
__global__ __launch_bounds__(256) void k_q(const float* __restrict__ x,
                                           const float* __restrict__ qs_w) {
    int og = blockIdx.x % 96;
    int t  = blockIdx.x / 96;
    __shared__ float xs[2 * C];
    for (int i = threadIdx.x; i < 2 * C; i += 256) {
        int b = i / C, c = i % C;
        xs[i] = x[((long)b * NTOK + t) * C + c];
    }
    __syncthreads();
    int warp = threadIdx.x >> 5, lane = threadIdx.x & 31;
    int o = og * 8 + warp;
    const float* wrow = qs_w + ((long)t * C + o) * C;
    float s0 = 0.f, s1 = 0.f;
    #pragma unroll 8
    for (int c = lane; c < C; c += 32) {
        float w = wrow[c];
        s0 += xs[c] * w;
        s1 += xs[C + c] * w;
    }
    s0 = warp_sum(s0);
    s1 = warp_sum(s1);
    if (lane == 0) {
        g_q[(0 * T + t) * C + o] = s0;
        g_q[(1 * T + t) * C + o] = s1;
    }
}

// ---------------- K2: qk[b,j,c] = sum_dd q[b,t,h*64+dd] * kv_w[h*64+dd, c] --
__global__ __launch_bounds__(128) void k_qk(const float* __restrict__ kv_w) {
    int ch = blockIdx.x % 6;
    int j  = blockIdx.x / 6;
    int t = j & 3, h = j >> 2;
    __shared__ float qs[2 * D];
    {
        int b = threadIdx.x >> 6, dd = threadIdx.x & 63;
        qs[threadIdx.x] = g_q[(b * T + t) * C + h * D + dd];
    }
    __syncthreads();
    int c = ch * 128 + threadIdx.x;
    float a0 = 0.f, a1 = 0.f;
    #pragma unroll 8
    for (int dd = 0; dd < D; dd++) {
        float w = kv_w[(long)(h * D + dd) * C + c];
        a0 += qs[dd] * w;
        a1 += qs[D + dd] * w;
    }
    g_qk[((long)(0 * J + j)) * C + c] = a0;
    g_qk[((long)(1 * J + j)) * C + c] = a1;
}

// ---------------- K3: partial attn over a c-quarter + output zeroing --------
// grid (64 m-tiles, B, 4 c-quarters) = 512 CTAs, occ 4. Each CTA also zeros
// its 3075-float4 slice of out (hidden under the compute pipeline).
#define CHUNK 32
#define NCH   (CPER / CHUNK)           // 6
#define QK_FL (48 * CHUNK)             // 1536
#define FSTR  34
#define STAGE_FL (QK_FL + 64 * FSTR)   // 3712 floats = 14848 B/stage
__global__ __launch_bounds__(256, 4) void k_attn(const float* __restrict__ x,
                                                 float4* __restrict__ out4) {
    extern __shared__ __align__(16) float sm[];   // 2 * STAGE_FL floats
    const int b  = blockIdx.y;
    const int m0 = blockIdx.x * 64;
    const int cs = blockIdx.z;
    const int tid  = threadIdx.x;
    const int warp = tid >> 5;
    const int lane = tid & 31;
    const int cr = tid >> 4;      // copy row base 0..15
    const int cp0 = tid & 15;     // copy pair    0..15

    const float* qsrc0 = g_qk + (long)b * J * C + cs * CPER
                       + (long)cr * C + cp0 * 2;               // +u*16*C
    const float* fsrc0 = x + ((long)b * NTOK + T + m0) * C + cs * CPER
                       + (long)cr * C + cp0 * 2;               // +u*16*C
    unsigned qdst0 = (unsigned)__cvta_generic_to_shared(
                         &sm[cr * CHUNK + cp0 * 2]);           // +u*2048B
    unsigned fdst0 = (unsigned)__cvta_generic_to_shared(
                         &sm[QK_FL + cr * FSTR + cp0 * 2]);    // +u*2176B

    unsigned long long acc[6][2];
    #pragma unroll
    for (int i = 0; i < 6; i++) { acc[i][0] = 0ull; acc[i][1] = 0ull; }

    #pragma unroll
    for (int u = 0; u < 3; u++) cp8(qdst0 + u * 2048, qsrc0 + u * 16 * C);
    #pragma unroll
    for (int u = 0; u < 4; u++) cp8(fdst0 + u * 2176, fsrc0 + u * 16 * C);
    asm volatile("cp.async.commit_group;\n" ::: "memory");

    // zero this CTA's slice of the output (overlaps the pipeline)
    {
        int ci = blockIdx.x + 64 * blockIdx.y + 64 * B * blockIdx.z;
        long zb = (long)ci * Z4CTA;
        float4 z = make_float4(0.f, 0.f, 0.f, 0.f);
        #pragma unroll
        for (int u = 0; u < 12; u++) out4[zb + u * 256 + tid] = z;
        if (tid < 3) out4[zb + 12 * 256 + tid] = z;
    }

    for (int ic = 0; ic < NCH; ic++) {
        if (ic < NCH - 1) {
            unsigned so = ((ic + 1) & 1) * (unsigned)(STAGE_FL * 4);
            int cc = (ic + 1) * CHUNK;
            #pragma unroll
            for (int u = 0; u < 3; u++)
                cp8(qdst0 + so + u * 2048, qsrc0 + cc + u * 16 * C);
            #pragma unroll
            for (int u = 0; u < 4; u++)
                cp8(fdst0 + so + u * 2176, fsrc0 + cc + u * 16 * C);
            asm volatile("cp.async.commit_group;\n" ::: "memory");
            asm volatile("cp.async.wait_group 1;\n" ::: "memory");
        } else {
            asm volatile("cp.async.wait_group 0;\n" ::: "memory");
        }
        __syncthreads();
        const float* s_qk = sm + (ic & 1) * STAGE_FL;
        const float* s_ft = s_qk + QK_FL;
        #pragma unroll
        for (int cp = 0; cp < 16; cp++) {
            unsigned long long f0 =
                *(const unsigned long long*)&s_ft[lane * FSTR + cp * 2];
            unsigned long long f1 =
                *(const unsigned long long*)&s_ft[(lane + 32) * FSTR + cp * 2];
            #pragma unroll
            for (int i = 0; i < 6; i++) {
                unsigned long long qv =
                    *(const unsigned long long*)&s_qk[(warp * 6 + i) * CHUNK + cp * 2];
                ffma2(acc[i][0], qv, f0);
                ffma2(acc[i][1], qv, f1);
            }
        }
        __syncthreads();
    }
    #pragma unroll
    for (int i = 0; i < 6; i++) {
        int j = warp * 6 + i;
        float* row = g_attn2[cs] + ((long)(b * J + j)) * M + m0;
        U64F2 u0; u0.u = acc[i][0];
        U64F2 u1; u1.u = acc[i][1];
        row[lane]      = (u0.f.x + u0.f.y) * SCALE;
        row[lane + 32] = (u1.f.x + u1.f.y) * SCALE;
    }
}

// ---------------- K4: fused top-2 + softmax (ticket merge) ------------------
__device__ __forceinline__ bool better(float v, int i, float bv, int bi) {
    return (v > bv) || (v == bv && (unsigned)i < (unsigned)bi);
}
// merge sorted pair (v0>=v1) with sorted pair (c0>=c1); indices all distinct
__device__ __forceinline__ void merge2(float &v0, int &i0, float &v1, int &i1,
                                       float c0, int jc, float c1, int jd) {
    float n0, n1; int m0i, m1i;
    if (better(v0, i0, c0, jc)) {
        n0 = v0; m0i = i0;
        if (better(v1, i1, c0, jc)) { n1 = v1; m1i = i1; }
        else                        { n1 = c0; m1i = jc; }
    } else {
        n0 = c0; m0i = jc;
        if (better(v0, i0, c1, jd)) { n1 = v0; m1i = i0; }
        else                        { n1 = c1; m1i = jd; }
    }
    v0 = n0; i0 = m0i; v1 = n1; i1 = m1i;
}

__global__ __launch_bounds__(256) void k_top2() {
    const int row   = blockIdx.y;          // 0..95
    const int mtile = blockIdx.x;          // 0..7
    const long base = (long)row * M + mtile * MTS;
    int tid = threadIdx.x, warp = tid >> 5, lane = tid & 31;
    int mm = tid * 2;                      // 0..510 within tile
    float2 a0 = *(const float2*)(g_attn2[0] + base + mm);
    float2 a1 = *(const float2*)(g_attn2[1] + base + mm);
    float2 a2 = *(const float2*)(g_attn2[2] + base + mm);
    float2 a3 = *(const float2*)(g_attn2[3] + base + mm);
    int gm = mtile * MTS + mm;
    float s0 = (a0.x + a1.x) + (a2.x + a3.x);
    float s1 = (a0.y + a1.y) + (a2.y + a3.y);
    float v0, v1; int i0, i1;
    if (better(s1, gm + 1, s0, gm)) { v0 = s1; i0 = gm + 1; v1 = s0; i1 = gm; }
    else                            { v0 = s0; i0 = gm;     v1 = s1; i1 = gm + 1; }

    // warp shuffle merge (both sides always sorted pairs)
    #pragma unroll
    for (int s = 16; s >= 1; s >>= 1) {
        float p0 = __shfl_down_sync(0xffffffffu, v0, s);
        float p1 = __shfl_down_sync(0xffffffffu, v1, s);
        int   q0 = __shfl_down_sync(0xffffffffu, i0, s);
        int   q1 = __shfl_down_sync(0xffffffffu, i1, s);
        merge2(v0, i0, v1, i1, p0, q0, p1, q1);
    }
    __shared__ float wv0[8], wv1[8];
    __shared__ int   wi0[8], wi1[8];
    if (lane == 0) { wv0[warp] = v0; wi0[warp] = i0; wv1[warp] = v1; wi1[warp] = i1; }
    __syncthreads();
    if (warp == 0) {
        if (lane < 8) { v0 = wv0[lane]; i0 = wi0[lane]; v1 = wv1[lane]; i1 = wi1[lane]; }
        #pragma unroll
        for (int s = 4; s >= 1; s >>= 1) {
            float p0 = __shfl_down_sync(0xffffffffu, v0, s);
            float p1 = __shfl_down_sync(0xffffffffu, v1, s);
            int   q0 = __shfl_down_sync(0xffffffffu, i0, s);
            int   q1 = __shfl_down_sync(0xffffffffu, i1, s);
            merge2(v0, i0, v1, i1, p0, q0, p1, q1);
        }
        if (lane == 0) {
            g_cv[row][mtile][0] = v0;  g_cv[row][mtile][1] = v1;
            g_ci[row][mtile][0] = i0;  g_ci[row][mtile][1] = i1;
            __threadfence();
            int old = atomicAdd(&g_ticket[row], 1);
            if (old == MT - 1) {
                __threadfence();
                float b0 = g_cv[row][0][0], b1 = g_cv[row][0][1];
                int   j0 = g_ci[row][0][0], j1 = g_ci[row][0][1];
                #pragma unroll
                for (int e = 1; e < MT; e++)
                    merge2(b0, j0, b1, j1,
                           g_cv[row][e][0], g_ci[row][e][0],
                           g_cv[row][e][1], g_ci[row][e][1]);
                float e1 = __expf(b1 - b0);
                float inv = 1.f / (1.f + e1);
                g_topi[row * K + 0] = j0;
                g_topi[row * K + 1] = j1;
                g_topw[row * K + 0] = inv;
                g_topw[row * K + 1] = e1 * inv;
                g_ticket[row] = 0;    // self-reset for next graph replay
            }
        }
    }
}

// ---------------- K5a: v-projection slices ----------------------------------
// grid (4 dd-quarters, H, B) = 96 CTAs. kv_w v-slice for head h read ONCE per
// (b,h,quarter) and shared across all 8 (t,k) selections.
// g_slice[b][h][t][dd] = w0*<f(t,0), kv_w[C+hD+dd,:]> + w1*<f(t,1), ...>
__global__ __launch_bounds__(256) void k_vproj(const float* __restrict__ x,
                                               const float* __restrict__ kv_w) {
    int qd = blockIdx.x;   // dd quarter 0..3
    int h  = blockIdx.y;
    int b  = blockIdx.z;
    int tid = threadIdx.x, warp = tid >> 5, lane = tid & 31;
    __shared__ __align__(16) float fs[8][C];    // rows (t*2+k)
    for (int r = 0; r < 8; r++) {
        int m = g_topi[(b * J + (h * 4 + (r >> 1))) * K + (r & 1)];
        for (int i = tid; i < C; i += 256)
            fs[r][i] = x[((long)b * NTOK + T + m) * C + i];
    }
    __syncthreads();
    #pragma unroll
    for (int u = 0; u < 2; u++) {
        int dd = qd * 16 + warp * 2 + u;
        const float* kw = kv_w + (long)(C + h * D + dd) * C;
        float a[8];
        #pragma unroll
        for (int r = 0; r < 8; r++) a[r] = 0.f;
        #pragma unroll 2
        for (int c = lane; c < C; c += 32) {
            float w = kw[c];
            #pragma unroll
            for (int r = 0; r < 8; r++) a[r] += fs[r][c] * w;
        }
        #pragma unroll
        for (int r = 0; r < 8; r++) a[r] = warp_sum(a[r]);
        if (lane == 0) {
            #pragma unroll
            for (int t = 0; t < 4; t++) {
                float w0 = g_topw[(b * J + h * 4 + t) * K + 0];
                float w1 = g_topw[(b * J + h * 4 + t) * K + 1];
                g_slice[((b * H + h) * T + t) * D + dd] =
                    w0 * a[t * 2] + w1 * a[t * 2 + 1];
            }
        }
    }
}

// ---------------- K5b: expert scatter + fused token output ------------------
// grid (J, 3 o-chunks) = 144 CTAs. ew row slice read ONCE, used for 6 dots
// (2 batches x {feat-k0, feat-k1, token}).
__global__ __launch_bounds__(256) void k_scatter(const float* __restrict__ x,
                                                 const float* __restrict__ experts_w,
                                                 float* __restrict__ out) {
    int j  = blockIdx.x;
    int oq = blockIdx.y;
    int t = j & 3, h = j >> 2;
    int tid = threadIdx.x;
    __shared__ __align__(16) float f0h[2][D], f1h[2][D], sl[2][D];
    __shared__ float w0s[2], w1s[2];
    __shared__ int   m0s[2], m1s[2];
    if (tid < 2) {
        int b = tid;
        m0s[b] = g_topi[(b * J + j) * K + 0];
        m1s[b] = g_topi[(b * J + j) * K + 1];
        w0s[b] = g_topw[(b * J + j) * K + 0];
        w1s[b] = g_topw[(b * J + j) * K + 1];
    }
    __syncthreads();
    if (tid < 128) {
        int b = tid >> 6, i = tid & 63;
        f0h[b][i] = x[((long)b * NTOK + T + m0s[b]) * C + h * D + i];
        f1h[b][i] = x[((long)b * NTOK + T + m1s[b]) * C + h * D + i];
        sl[b][i]  = g_slice[((b * H + h) * T + t) * D + i];
    }
    __syncthreads();

    int o = oq * 256 + tid;
    const float4* ew4 = (const float4*)(experts_w + ((long)t * C + o) * C + h * D);
    const float4* fa0 = (const float4*)f0h[0];
    const float4* fb0 = (const float4*)f1h[0];
    const float4* sa0 = (const float4*)sl[0];
    const float4* fa1 = (const float4*)f0h[1];
    const float4* fb1 = (const float4*)f1h[1];
    const float4* sa1 = (const float4*)sl[1];
    float s0a = 0.f, s1a = 0.f, sta = 0.f;
    float s0b = 0.f, s1b = 0.f, stb = 0.f;
    #pragma unroll
    for (int q = 0; q < 16; q++) {
        float4 e = ew4[q];
        float4 u0 = fa0[q], v0 = fb0[q], z0 = sa0[q];
        float4 u1 = fa1[q], v1 = fb1[q], z1 = sa1[q];
        s0a += u0.x * e.x + u0.y * e.y + u0.z * e.z + u0.w * e.w;
        s1a += v0.x * e.x + v0.y * e.y + v0.z * e.z + v0.w * e.w;
        sta += z0.x * e.x + z0.y * e.y + z0.z * e.z + z0.w * e.w;
        s0b += u1.x * e.x + u1.y * e.y + u1.z * e.z + u1.w * e.w;
        s1b += v1.x * e.x + v1.y * e.y + v1.z * e.z + v1.w * e.w;
        stb += z1.x * e.x + z1.y * e.y + z1.z * e.z + z1.w * e.w;
    }
    atomicAdd(&out[((long)0 * NTOK + T + m0s[0]) * C + o], w0s[0] * s0a);
    atomicAdd(&out[((long)0 * NTOK + T + m1s[0]) * C + o], w1s[0] * s1a);
    atomicAdd(&out[((long)0 * NTOK + t) * C + o], sta);
    atomicAdd(&out[((long)1 * NTOK + T + m0s[1]) * C + o], w0s[1] * s0b);
    atomicAdd(&out[((long)1 * NTOK + T + m1s[1]) * C + o], w1s[1] * s1b);
    atomicAdd(&out[((long)1 * NTOK + t) * C + o], stb);
}

// ---------------- launch ----------------------------------------------------
extern "C" void kernel_launch(void* const* d_in, const int* in_sizes, int n_in,
                              void* d_out, int out_size) {
    const float* x         = (const float*)d_in[0];
    const float* qs_w      = (const float*)d_in[1];
    const float* kv_w      = (const float*)d_in[2];
    const float* experts_w = (const float*)d_in[3];
    float* out = (float*)d_out;

    k_q<<<384, 256>>>(x, qs_w);
    k_qk<<<288, 128>>>(kv_w);
    k_attn<<<dim3(64, B, CSP), 256, 2 * STAGE_FL * 4>>>(x, (float4*)out);
    k_top2<<<dim3(MT, B * J), 256>>>();
    k_vproj<<<dim3(4, H, B), 256>>>(x, kv_w);
    k_scatter<<<dim3(J, 3), 256>>>(x, experts_w, out);
}